// round 9
// baseline (speedup 1.0000x reference)
#include <cuda_runtime.h>
#include <cuda_fp16.h>
#include <math.h>
#include <stdint.h>

#define NN 50000
#define EE 1200000
#define GG 256
#define NBLK 196   // ceil(NN/256)

// ---------------- scratch ----------------------------------------------------
__device__ float   g_hx[NN * 64];     // (x @ conv1_W) * dinv[n]  (fp32, self term)
__device__ __half2 g_hx16[NN * 32];   // fp16 copy for gather
__device__ float   g_h[NN * 64];      // running node features
__device__ float   g_u[NN * 64];      // LN+PReLU output (fp32, self term)
__device__ __half2 g_u16[NN * 32];    // fp16 copy for gather
__device__ __half2 g_agg16[NN * 32];  // GEN aggregation output (fp16, MLP input)
__device__ float   g_xcat[NN * 256];  // JK concat buffer
__device__ int     g_hist[NN];
__device__ int     g_rowptr[NN + 1];  // consumed by scatter: ends as row-ENDS
__device__ int     g_colsrc[EE];
__device__ float   g_dinv[NN];
__device__ int     g_gstart[GG + 1];
__device__ __half  g_W1T[3 * 8192];   // W1^T fp16: [layer][o=128][k=64]
__device__ __half  g_W2T[3 * 8192];   // W2^T fp16: [layer][n=64][k=128]

__device__ __forceinline__ uint32_t smem_u32(const void* p) {
    uint32_t a;
    asm("{ .reg .u64 t; cvta.to.shared.u64 t, %1; cvt.u32.u64 %0, t; }" : "=r"(a) : "l"(p));
    return a;
}

// ---------------- init ------------------------------------------------------
__global__ void k_init() {
    int i = blockIdx.x * blockDim.x + threadIdx.x;
    if (i < NN) g_hist[i] = 0;
}

// ---------------- CSR build -------------------------------------------------
__global__ void k_hist(const int* __restrict__ dst) {
    int i = blockIdx.x * blockDim.x + threadIdx.x;
    if (i < EE) atomicAdd(&g_hist[dst[i]], 1);
}

__device__ __forceinline__ int wscan_incl32(int x, int lane) {
#pragma unroll
    for (int o = 1; o < 32; o <<= 1) {
        int y = __shfl_up_sync(0xffffffffu, x, o);
        if (lane >= o) x += y;
    }
    return x;
}

// single-kernel coalesced scan of hist -> rowptr (+ dinv)
__global__ void k_scanall() {
    __shared__ int ws[32];
    __shared__ int sbase;
    int tid = threadIdx.x;           // 1024
    int lane = tid & 31, wid = tid >> 5;
    if (tid == 0) sbase = 0;
    __syncthreads();
    for (int chunk = 0; chunk < NN; chunk += 1024) {
        int i = chunk + tid;
        int v = (i < NN) ? g_hist[i] : 0;
        int incl = wscan_incl32(v, lane);
        if (lane == 31) ws[wid] = incl;
        __syncthreads();
        if (tid < 32) {
            int b = ws[tid];
#pragma unroll
            for (int o = 1; o < 32; o <<= 1) {
                int y = __shfl_up_sync(0xffffffffu, b, o);
                if (tid >= o) b += y;
            }
            ws[tid] = b;
        }
        __syncthreads();
        int base = sbase + ((wid > 0) ? ws[wid - 1] : 0);
        if (i < NN) {
            g_rowptr[i] = base + incl - v;
            g_dinv[i] = rsqrtf((float)(v + 1));
        }
        __syncthreads();
        if (tid == 0) sbase += ws[31];
        __syncthreads();
    }
}

// scatter consumes rowptr: afterwards g_rowptr[n] == original rowptr[n+1]
__global__ void k_scatter(const int* __restrict__ src, const int* __restrict__ dst) {
    int i = blockIdx.x * blockDim.x + threadIdx.x;
    if (i < EE) {
        int d = dst[i];
        int pos = atomicAdd(&g_rowptr[d], 1);
        g_colsrc[pos] = src[i];
    }
}

// graph boundaries from sorted batch_idx
__global__ void k_gstart(const int* __restrict__ batch) {
    int n = blockIdx.x * blockDim.x + threadIdx.x;
    if (n >= NN) return;
    int b = batch[n];
    int prev = (n == 0) ? -1 : batch[n - 1];
    for (int g = prev + 1; g <= b; g++) g_gstart[g] = n;
    if (n == NN - 1) {
        for (int g = b + 1; g <= GG; g++) g_gstart[g] = NN;
    }
}

// ---------------- weight prep: fp16 transposed ------------------------------
__global__ void k_wprep(const float* __restrict__ W1, const float* __restrict__ W2) {
    int idx = blockIdx.x * blockDim.x + threadIdx.x;
    if (idx < 3 * 8192) {
        int l = idx >> 13, r = idx & 8191;
        int o = r >> 6, k = r & 63;
        g_W1T[idx] = __float2half(W1[l * 8192 + k * 128 + o]);
    } else if (idx < 6 * 8192) {
        int t = idx - 3 * 8192;
        int l = t >> 13, r = t & 8191;
        int n = r >> 7, k = r & 127;
        g_W2T[t] = __float2half(W2[l * 8192 + k * 64 + n]);
    }
}

// ---------------- x @ conv1_W, pre-scaled by dinv[n]; fp32 + fp16 ------------
__global__ void k_hx(const float* __restrict__ x, const float* __restrict__ W) {
    int idx = blockIdx.x * blockDim.x + threadIdx.x;
    if (idx >= NN * 32) return;
    int n = idx >> 5, p = idx & 31;
    float a0 = 0.f, a1 = 0.f;
#pragma unroll
    for (int f = 0; f < 5; f++) {
        float xv = x[n * 5 + f];
        a0 += xv * W[f * 64 + 2 * p];
        a1 += xv * W[f * 64 + 2 * p + 1];
    }
    float dn = g_dinv[n];
    a0 *= dn;
    a1 *= dn;
    float2 o;
    o.x = a0; o.y = a1;
    *reinterpret_cast<float2*>(&g_hx[n * 64 + 2 * p]) = o;
    g_hx16[n * 32 + p] = __floats2half2_rn(a0, a1);
}

// ---- GCNConv aggregate + BN + ReLU + fused layer-0 LN+PReLU -----------------
__global__ void k_gcn(const float* __restrict__ cb, const float* __restrict__ bg,
                      const float* __restrict__ bb, const float* __restrict__ lg,
                      const float* __restrict__ lb, const float* __restrict__ pa) {
    int tid = threadIdx.x;
    int n = blockIdx.x * 8 + (tid >> 5);
    int l = tid & 31;
    if (n >= NN) return;
    int b = (n == 0) ? 0 : g_rowptr[n - 1];
    int e = g_rowptr[n];
    float a0 = 0.f, a1 = 0.f;
    int i = b;
    for (; i + 8 <= e; i += 8) {
        int s0 = g_colsrc[i], s1 = g_colsrc[i + 1];
        int s2 = g_colsrc[i + 2], s3 = g_colsrc[i + 3];
        int s4 = g_colsrc[i + 4], s5 = g_colsrc[i + 5];
        int s6 = g_colsrc[i + 6], s7 = g_colsrc[i + 7];
        float2 f0 = __half22float2(g_hx16[s0 * 32 + l]);
        float2 f1 = __half22float2(g_hx16[s1 * 32 + l]);
        float2 f2 = __half22float2(g_hx16[s2 * 32 + l]);
        float2 f3 = __half22float2(g_hx16[s3 * 32 + l]);
        float2 f4 = __half22float2(g_hx16[s4 * 32 + l]);
        float2 f5 = __half22float2(g_hx16[s5 * 32 + l]);
        float2 f6 = __half22float2(g_hx16[s6 * 32 + l]);
        float2 f7 = __half22float2(g_hx16[s7 * 32 + l]);
        a0 += ((f0.x + f1.x) + (f2.x + f3.x)) + ((f4.x + f5.x) + (f6.x + f7.x));
        a1 += ((f0.y + f1.y) + (f2.y + f3.y)) + ((f4.y + f5.y) + (f6.y + f7.y));
    }
    for (; i < e; i++) {
        float2 f = __half22float2(g_hx16[g_colsrc[i] * 32 + l]);
        a0 += f.x;
        a1 += f.y;
    }
    float2 hx = *reinterpret_cast<const float2*>(&g_hx[n * 64 + 2 * l]);
    float dn = g_dinv[n];
    const float BNS = rsqrtf(1.f + 1e-5f);
    float v0 = (a0 + hx.x) * dn + cb[2 * l];
    float v1 = (a1 + hx.y) * dn + cb[2 * l + 1];
    v0 = fmaxf(v0 * (bg[2 * l] * BNS) + bb[2 * l], 0.f);
    v1 = fmaxf(v1 * (bg[2 * l + 1] * BNS) + bb[2 * l + 1], 0.f);
    float2 o; o.x = v0; o.y = v1;
    *reinterpret_cast<float2*>(&g_h[n * 64 + 2 * l]) = o;
    *reinterpret_cast<float2*>(&g_xcat[n * 256 + 2 * l]) = o;
    // fused layer-0 LayerNorm + PReLU
    float s = v0 + v1;
    float q = v0 * v0 + v1 * v1;
#pragma unroll
    for (int off = 16; off > 0; off >>= 1) {
        s += __shfl_xor_sync(0xffffffffu, s, off);
        q += __shfl_xor_sync(0xffffffffu, q, off);
    }
    float mu = s * (1.f / 64.f);
    float var = q * (1.f / 64.f) - mu * mu;
    float rs = rsqrtf(var + 1e-5f);
    float y0 = (v0 - mu) * rs * lg[2 * l] + lb[2 * l];
    y0 = (y0 >= 0.f) ? y0 : pa[2 * l] * y0;
    float y1 = (v1 - mu) * rs * lg[2 * l + 1] + lb[2 * l + 1];
    y1 = (y1 >= 0.f) ? y1 : pa[2 * l + 1] * y1;
    float2 uo; uo.x = y0; uo.y = y1;
    *reinterpret_cast<float2*>(&g_u[n * 64 + 2 * l]) = uo;
    g_u16[n * 32 + l] = __floats2half2_rn(y0, y1);
}

// ---------------- GENConv softmax aggregation (warp per node, fp16) ----------
__global__ void k_gen(const float* __restrict__ gen_t, int layer) {
    int tid = threadIdx.x;
    int n = blockIdx.x * 8 + (tid >> 5);
    int l = tid & 31;
    if (n >= NN) return;
    float t = __ldg(&gen_t[layer]);
    int b = (n == 0) ? 0 : g_rowptr[n - 1];
    int e = g_rowptr[n];
    float s0 = 0.f, s1 = 0.f, ac0 = 0.f, ac1 = 0.f;
    int i = b;
    for (; i + 8 <= e; i += 8) {
#pragma unroll
        for (int z = 0; z < 8; z += 4) {
            int sA = g_colsrc[i + z], sB = g_colsrc[i + z + 1];
            int sC = g_colsrc[i + z + 2], sD = g_colsrc[i + z + 3];
            float2 fA = __half22float2(g_u16[sA * 32 + l]);
            float2 fB = __half22float2(g_u16[sB * 32 + l]);
            float2 fC = __half22float2(g_u16[sC * 32 + l]);
            float2 fD = __half22float2(g_u16[sD * 32 + l]);
            float vA0 = fmaxf(fA.x, 0.f) + 1e-7f, vA1 = fmaxf(fA.y, 0.f) + 1e-7f;
            float vB0 = fmaxf(fB.x, 0.f) + 1e-7f, vB1 = fmaxf(fB.y, 0.f) + 1e-7f;
            float vC0 = fmaxf(fC.x, 0.f) + 1e-7f, vC1 = fmaxf(fC.y, 0.f) + 1e-7f;
            float vD0 = fmaxf(fD.x, 0.f) + 1e-7f, vD1 = fmaxf(fD.y, 0.f) + 1e-7f;
            float eA0 = __expf(vA0 * t), eA1 = __expf(vA1 * t);
            float eB0 = __expf(vB0 * t), eB1 = __expf(vB1 * t);
            float eC0 = __expf(vC0 * t), eC1 = __expf(vC1 * t);
            float eD0 = __expf(vD0 * t), eD1 = __expf(vD1 * t);
            s0 += (eA0 + eB0) + (eC0 + eD0);
            s1 += (eA1 + eB1) + (eC1 + eD1);
            ac0 += (vA0 * eA0 + vB0 * eB0) + (vC0 * eC0 + vD0 * eD0);
            ac1 += (vA1 * eA1 + vB1 * eB1) + (vC1 * eC1 + vD1 * eD1);
        }
    }
    for (; i < e; i++) {
        float2 f = __half22float2(g_u16[g_colsrc[i] * 32 + l]);
        float v0 = fmaxf(f.x, 0.f) + 1e-7f;
        float v1 = fmaxf(f.y, 0.f) + 1e-7f;
        float e0 = __expf(v0 * t), e1 = __expf(v1 * t);
        s0 += e0; s1 += e1;
        ac0 += v0 * e0; ac1 += v1 * e1;
    }
    float2 u = *reinterpret_cast<const float2*>(&g_u[n * 64 + 2 * l]);
    float o0 = ((e > b) ? (ac0 / s0) : 0.f) + u.x;
    float o1 = ((e > b) ? (ac1 / s1) : 0.f) + u.y;
    g_agg16[n * 32 + l] = __floats2half2_rn(o0, o1);
}

// ---------------- HMMA fused MLP + fused next-layer LN -----------------------
#define STA 72    // halves per A row (144B)
#define STW2 136  // halves per W2 row (272B)

__device__ __forceinline__ void ldmx4(uint32_t addr, uint32_t& a0, uint32_t& a1,
                                      uint32_t& a2, uint32_t& a3) {
    asm volatile("ldmatrix.sync.aligned.m8n8.x4.shared.b16 {%0,%1,%2,%3}, [%4];"
                 : "=r"(a0), "=r"(a1), "=r"(a2), "=r"(a3) : "r"(addr));
}
__device__ __forceinline__ void ldmx2(uint32_t addr, uint32_t& b0, uint32_t& b1) {
    asm volatile("ldmatrix.sync.aligned.m8n8.x2.shared.b16 {%0,%1}, [%2];"
                 : "=r"(b0), "=r"(b1) : "r"(addr));
}
__device__ __forceinline__ void mma16816(float* c, const uint32_t* a, const uint32_t* b) {
    asm volatile("mma.sync.aligned.m16n8k16.row.col.f32.f16.f16.f32 "
                 "{%0,%1,%2,%3}, {%4,%5,%6,%7}, {%8,%9}, {%0,%1,%2,%3};"
                 : "+f"(c[0]), "+f"(c[1]), "+f"(c[2]), "+f"(c[3])
                 : "r"(a[0]), "r"(a[1]), "r"(a[2]), "r"(a[3]), "r"(b[0]), "r"(b[1]));
}

__global__ void __launch_bounds__(256)
k_mma(const float* __restrict__ b1, const float* __restrict__ bng,
      const float* __restrict__ bnb, const float* __restrict__ b2,
      const float* __restrict__ lg, const float* __restrict__ lb,
      const float* __restrict__ pa, int layer) {
    extern __shared__ char smem[];
    float*  mpar = (float*)smem;              // 128
    float*  apar = mpar + 128;                // 128
    __half* sA   = (__half*)(apar + 128);     // 128*STA
    __half* sW1  = sA + 128 * STA;            // 128*STA
    __half* sW2  = sW1 + 128 * STA;           // 64*STW2
    int tid = threadIdx.x;
    int n0 = blockIdx.x * 128;

    if (tid < 128) {
        const float BNS = rsqrtf(1.f + 1e-5f);
        float m = __ldg(&bng[tid]) * BNS;
        mpar[tid] = m;
        apar[tid] = __ldg(&b1[tid]) * m + __ldg(&bnb[tid]);
    }
    for (int i = tid; i < 128 * 32; i += 256) {
        int r = i >> 5, p = i & 31;
        int n = n0 + r;
        __half2 v = (n < NN) ? g_agg16[n * 32 + p] : __floats2half2_rn(0.f, 0.f);
        *(__half2*)&sA[r * STA + 2 * p] = v;
    }
    const __half* w1p = g_W1T + layer * 8192;
    for (int i = tid; i < 128 * 32; i += 256) {
        int r = i >> 5, p = i & 31;
        *(__half2*)&sW1[r * STA + 2 * p] = *(const __half2*)&w1p[r * 64 + 2 * p];
    }
    const __half* w2p = g_W2T + layer * 8192;
    for (int i = tid; i < 64 * 64; i += 256) {
        int r = i >> 6, p = i & 63;
        *(__half2*)&sW2[r * STW2 + 2 * p] = *(const __half2*)&w2p[r * 128 + 2 * p];
    }
    __syncthreads();

    int wid = tid >> 5, lane = tid & 31;
    int m0 = wid * 16;

    // ---- stage 1 ----
    float c[16][4];
#pragma unroll
    for (int nt = 0; nt < 16; nt++)
#pragma unroll
        for (int q = 0; q < 4; q++) c[nt][q] = 0.f;

    int arow = m0 + (lane & 7) + ((lane >> 3) & 1) * 8;
    int acolbase = (lane >> 4) * 8;
    int brow = (lane & 7);
    int bcolbase = ((lane >> 3) & 1) * 8;
#pragma unroll
    for (int kt = 0; kt < 4; kt++) {
        uint32_t a[4];
        ldmx4(smem_u32(&sA[arow * STA + kt * 16 + acolbase]), a[0], a[1], a[2], a[3]);
#pragma unroll
        for (int nt = 0; nt < 16; nt++) {
            uint32_t b[2];
            ldmx2(smem_u32(&sW1[(nt * 8 + brow) * STA + kt * 16 + bcolbase]), b[0], b[1]);
            mma16816(c[nt], a, b);
        }
    }

    // ---- epilogue 1 (BN+ReLU) -> stage-2 A fragments in registers ----
    int ob = (lane & 3) * 2;
    uint32_t az[8][4];
#pragma unroll
    for (int nt = 0; nt < 16; nt++) {
        int o0 = nt * 8 + ob, o1 = o0 + 1;
        float m0f = mpar[o0], m1f = mpar[o1];
        float a0f = apar[o0], a1f = apar[o1];
        float z0 = fmaxf(c[nt][0] * m0f + a0f, 0.f);
        float z1 = fmaxf(c[nt][1] * m1f + a1f, 0.f);
        float z2 = fmaxf(c[nt][2] * m0f + a0f, 0.f);
        float z3 = fmaxf(c[nt][3] * m1f + a1f, 0.f);
        __half2 p01 = __floats2half2_rn(z0, z1);
        __half2 p23 = __floats2half2_rn(z2, z3);
        az[nt >> 1][(nt & 1) * 2 + 0] = *(uint32_t*)&p01;
        az[nt >> 1][(nt & 1) * 2 + 1] = *(uint32_t*)&p23;
    }

    // ---- stage 2 ----
    float d[8][4];
#pragma unroll
    for (int nt = 0; nt < 8; nt++)
#pragma unroll
        for (int q = 0; q < 4; q++) d[nt][q] = 0.f;
#pragma unroll
    for (int kt = 0; kt < 8; kt++) {
#pragma unroll
        for (int nt = 0; nt < 8; nt++) {
            uint32_t b[2];
            ldmx2(smem_u32(&sW2[(nt * 8 + brow) * STW2 + kt * 16 + bcolbase]), b[0], b[1]);
            mma16816(d[nt], az[kt], b);
        }
    }

    // ---- epilogue 2: + b2 + residual -> h, xcat; fused LN -> u, u16 ----
    int r0 = n0 + m0 + (lane >> 2);
    int r1 = r0 + 8;
    int xoff = (layer + 1) * 64;
    float2 nh0[8], nh1[8];
    float sr0 = 0.f, qr0 = 0.f, sr1 = 0.f, qr1 = 0.f;
#pragma unroll
    for (int nt = 0; nt < 8; nt++) {
        int o0 = nt * 8 + ob;
        float bb0 = __ldg(&b2[o0]);
        float bb1 = __ldg(&b2[o0 + 1]);
        nh0[nt].x = 0.f; nh0[nt].y = 0.f; nh1[nt].x = 0.f; nh1[nt].y = 0.f;
        if (r0 < NN) {
            float2 hv = *(float2*)&g_h[r0 * 64 + o0];
            nh0[nt].x = hv.x + d[nt][0] + bb0;
            nh0[nt].y = hv.y + d[nt][1] + bb1;
            *(float2*)&g_h[r0 * 64 + o0] = nh0[nt];
            *(float2*)&g_xcat[r0 * 256 + xoff + o0] = nh0[nt];
        }
        if (r1 < NN) {
            float2 hv = *(float2*)&g_h[r1 * 64 + o0];
            nh1[nt].x = hv.x + d[nt][2] + bb0;
            nh1[nt].y = hv.y + d[nt][3] + bb1;
            *(float2*)&g_h[r1 * 64 + o0] = nh1[nt];
            *(float2*)&g_xcat[r1 * 256 + xoff + o0] = nh1[nt];
        }
        sr0 += nh0[nt].x + nh0[nt].y;
        qr0 += nh0[nt].x * nh0[nt].x + nh0[nt].y * nh0[nt].y;
        sr1 += nh1[nt].x + nh1[nt].y;
        qr1 += nh1[nt].x * nh1[nt].x + nh1[nt].y * nh1[nt].y;
    }
    if (layer < 2) {
        // quad reduction (lanes sharing lane>>2 hold the same row)
        sr0 += __shfl_xor_sync(0xffffffffu, sr0, 1);
        sr0 += __shfl_xor_sync(0xffffffffu, sr0, 2);
        qr0 += __shfl_xor_sync(0xffffffffu, qr0, 1);
        qr0 += __shfl_xor_sync(0xffffffffu, qr0, 2);
        sr1 += __shfl_xor_sync(0xffffffffu, sr1, 1);
        sr1 += __shfl_xor_sync(0xffffffffu, sr1, 2);
        qr1 += __shfl_xor_sync(0xffffffffu, qr1, 1);
        qr1 += __shfl_xor_sync(0xffffffffu, qr1, 2);
        float mu0 = sr0 * (1.f / 64.f);
        float v0 = qr0 * (1.f / 64.f) - mu0 * mu0;
        float rs0 = rsqrtf(v0 + 1e-5f);
        float mu1 = sr1 * (1.f / 64.f);
        float v1 = qr1 * (1.f / 64.f) - mu1 * mu1;
        float rs1 = rsqrtf(v1 + 1e-5f);
#pragma unroll
        for (int nt = 0; nt < 8; nt++) {
            int o0 = nt * 8 + ob;
            float g0 = __ldg(&lg[o0]), g1 = __ldg(&lg[o0 + 1]);
            float be0 = __ldg(&lb[o0]), be1 = __ldg(&lb[o0 + 1]);
            float a0 = __ldg(&pa[o0]), a1 = __ldg(&pa[o0 + 1]);
            if (r0 < NN) {
                float y0 = (nh0[nt].x - mu0) * rs0 * g0 + be0;
                y0 = (y0 >= 0.f) ? y0 : a0 * y0;
                float y1 = (nh0[nt].y - mu0) * rs0 * g1 + be1;
                y1 = (y1 >= 0.f) ? y1 : a1 * y1;
                float2 uo; uo.x = y0; uo.y = y1;
                *(float2*)&g_u[r0 * 64 + o0] = uo;
                g_u16[r0 * 32 + (o0 >> 1)] = __floats2half2_rn(y0, y1);
            }
            if (r1 < NN) {
                float y0 = (nh1[nt].x - mu1) * rs1 * g0 + be0;
                y0 = (y0 >= 0.f) ? y0 : a0 * y0;
                float y1 = (nh1[nt].y - mu1) * rs1 * g1 + be1;
                y1 = (y1 >= 0.f) ? y1 : a1 * y1;
                float2 uo; uo.x = y0; uo.y = y1;
                *(float2*)&g_u[r1 * 64 + o0] = uo;
                g_u16[r1 * 32 + (o0 >> 1)] = __floats2half2_rn(y0, y1);
            }
        }
    }
}
#define MMA_SMEM (256 * 4 + (128 * STA + 128 * STA + 64 * STW2) * 2)

// ---------------- fused pooling + readout MLP --------------------------------
__global__ void k_poolread(const float* __restrict__ W1, const float* __restrict__ b1,
                           const float* __restrict__ W2, const float* __restrict__ b2,
                           const float* __restrict__ Wo, const float* __restrict__ bo,
                           float* __restrict__ out) {
    __shared__ float p[512];
    __shared__ float q1[128];
    __shared__ float q2[64];
    int g = blockIdx.x;
    int tid = threadIdx.x;   // 256
    int beg = g_gstart[g], end = g_gstart[g + 1];
    float sum = 0.f, mx = -INFINITY;
    for (int n = beg; n < end; n++) {
        float v = g_xcat[n * 256 + tid];
        sum += v;
        mx = fmaxf(mx, v);
    }
    float c = (float)(end - beg);
    p[tid] = sum / fmaxf(c, 1.f);
    p[256 + tid] = (end > beg) ? mx : 0.f;
    __syncthreads();
    if (tid < 128) {
        float a = b1[tid];
        for (int k = 0; k < 512; k++) a += p[k] * W1[k * 128 + tid];
        q1[tid] = fmaxf(a, 0.f);
    }
    __syncthreads();
    if (tid < 64) {
        float a = b2[tid];
        for (int k = 0; k < 128; k++) a += q1[k] * W2[k * 64 + tid];
        q2[tid] = fmaxf(a, 0.f);
    }
    __syncthreads();
    if (tid < 32) {
        float s = q2[tid] * Wo[tid] + q2[tid + 32] * Wo[tid + 32];
#pragma unroll
        for (int off = 16; off > 0; off >>= 1) s += __shfl_xor_sync(0xffffffffu, s, off);
        if (tid == 0) out[g] = s + bo[0];
    }
}

// ---------------- launch -----------------------------------------------------
extern "C" void kernel_launch(void* const* d_in, const int* in_sizes, int n_in,
                              void* d_out, int out_size) {
    const float* x        = (const float*)d_in[0];
    const int*   ei       = (const int*)d_in[1];
    const int*   batch    = (const int*)d_in[2];
    const float* conv1_W  = (const float*)d_in[3];
    const float* conv1_b  = (const float*)d_in[4];
    const float* bn1_g    = (const float*)d_in[5];
    const float* bn1_b    = (const float*)d_in[6];
    const float* ln_g     = (const float*)d_in[7];
    const float* ln_b     = (const float*)d_in[8];
    const float* prelu_a  = (const float*)d_in[9];
    const float* gen_t    = (const float*)d_in[10];
    const float* mlp_W1   = (const float*)d_in[11];
    const float* mlp_b1   = (const float*)d_in[12];
    const float* mlp_bn_g = (const float*)d_in[13];
    const float* mlp_bn_b = (const float*)d_in[14];
    const float* mlp_W2   = (const float*)d_in[15];
    const float* mlp_b2   = (const float*)d_in[16];
    const float* lin1_W   = (const float*)d_in[17];
    const float* lin1_b   = (const float*)d_in[18];
    const float* lin2_W   = (const float*)d_in[19];
    const float* lin2_b   = (const float*)d_in[20];
    const float* out_W    = (const float*)d_in[21];
    const float* out_b    = (const float*)d_in[22];
    float* out = (float*)d_out;

    const int* src = ei;
    const int* dst = ei + EE;

    static int smem_set = 0;
    if (!smem_set) {
        cudaFuncSetAttribute(k_mma, cudaFuncAttributeMaxDynamicSharedMemorySize, MMA_SMEM);
        smem_set = 1;
    }

    k_init<<<NBLK, 256>>>();
    k_hist<<<(EE + 255) / 256, 256>>>(dst);
    k_scanall<<<1, 1024>>>();
    k_scatter<<<(EE + 255) / 256, 256>>>(src, dst);
    k_gstart<<<NBLK, 256>>>(batch);
    k_wprep<<<192, 256>>>(mlp_W1, mlp_W2);
    k_hx<<<(NN * 32 + 255) / 256, 256>>>(x, conv1_W);
    k_gcn<<<(NN + 7) / 8, 256>>>(conv1_b, bn1_g, bn1_b, ln_g, ln_b, prelu_a);

    for (int i = 0; i < 3; i++) {
        k_gen<<<(NN + 7) / 8, 256>>>(gen_t, i);
        k_mma<<<(NN + 127) / 128, 256, MMA_SMEM>>>(
            mlp_b1 + i * 128, mlp_bn_g + i * 128, mlp_bn_b + i * 128, mlp_b2 + i * 64,
            ln_g + (i + 1 < 3 ? i + 1 : 0) * 64, ln_b + (i + 1 < 3 ? i + 1 : 0) * 64,
            prelu_a + (i + 1 < 3 ? i + 1 : 0) * 64, i);
    }

    k_poolread<<<GG, 256>>>(lin1_W, lin1_b, lin2_W, lin2_b, out_W, out_b, out);
}

// round 12
// speedup vs baseline: 1.1238x; 1.1238x over previous
#include <cuda_runtime.h>
#include <cuda_fp16.h>
#include <math.h>
#include <stdint.h>

#define NN 50000
#define EE 1200000
#define GG 256
#define NBLK 196   // ceil(NN/256)

// ---------------- scratch ----------------------------------------------------
__device__ float   g_hx[NN * 64];     // (x @ conv1_W) * dinv[n]  (fp32, self term)
__device__ __half2 g_hx16[NN * 32];   // fp16 copy for gather
__device__ float   g_h[NN * 64];      // running node features
__device__ __half2 g_u16[NN * 32];    // LN+PReLU output (fp16)
__device__ __half2 g_agg16[NN * 32];  // GEN aggregation output (fp16, MLP input)
__device__ float   g_xcat[NN * 256];  // JK concat buffer
__device__ int     g_hist[NN];
__device__ int     g_rowptr[NN + 1];  // consumed by scatter: ends as row-ENDS
__device__ int     g_colsrc[EE];
__device__ float   g_dinv[NN];
__device__ int     g_gstart[GG + 1];
__device__ __half  g_W1T[3 * 8192];   // W1^T fp16: [layer][o=128][k=64]
__device__ __half  g_W2T[3 * 8192];   // W2^T fp16: [layer][n=64][k=128]
__device__ int          g_blk_agg[NBLK];
__device__ int          g_blk_pref[NBLK];
__device__ volatile int g_blk_flag[NBLK];

__device__ __forceinline__ uint32_t smem_u32(const void* p) {
    uint32_t a;
    asm("{ .reg .u64 t; cvta.to.shared.u64 t, %1; cvt.u32.u64 %0, t; }" : "=r"(a) : "l"(p));
    return a;
}

// ---------------- init ------------------------------------------------------
__global__ void k_init() {
    int i = blockIdx.x * blockDim.x + threadIdx.x;
    if (i < NN) g_hist[i] = 0;
    if (i < NBLK) g_blk_flag[i] = 0;
}

// ---------------- CSR build -------------------------------------------------
__global__ void k_hist(const int* __restrict__ dst) {
    int i = blockIdx.x * blockDim.x + threadIdx.x;
    if (i < EE) atomicAdd(&g_hist[dst[i]], 1);
}

__device__ __forceinline__ int wscan_incl32(int x, int lane) {
#pragma unroll
    for (int o = 1; o < 32; o <<= 1) {
        int y = __shfl_up_sync(0xffffffffu, x, o);
        if (lane >= o) x += y;
    }
    return x;
}

// single-launch decoupled-lookback scan: hist -> rowptr (+ dinv)
__global__ void k_scanlb() {
    __shared__ int wsum[8];
    __shared__ int sexc;
    int tid = threadIdx.x, bid = blockIdx.x;
    int lane = tid & 31, wid = tid >> 5;
    int i = bid * 256 + tid;
    int v = (i < NN) ? g_hist[i] : 0;
    int incl = wscan_incl32(v, lane);
    if (lane == 31) wsum[wid] = incl;
    __syncthreads();
    if (tid < 8) {
        int b = wsum[tid];
#pragma unroll
        for (int o = 1; o < 8; o <<= 1) {
            int y = __shfl_up_sync(0xffu, b, o);
            if (tid >= o) b += y;
        }
        wsum[tid] = b;
    }
    __syncthreads();
    int wbase = (wid > 0) ? wsum[wid - 1] : 0;
    int total = wsum[7];
    if (tid == 0) {
        if (bid == 0) {
            g_blk_pref[0] = total;
            __threadfence();
            g_blk_flag[0] = 2;
            sexc = 0;
        } else {
            g_blk_agg[bid] = total;
            __threadfence();
            g_blk_flag[bid] = 1;
        }
    }
    if (bid > 0 && wid == 0) {
        int run = 0;
        int p = bid - 1;
        while (true) {
            int idx = p - lane;
            int f = 0, a = 0;
            if (idx >= 0) {
                while ((f = g_blk_flag[idx]) == 0) {}
                __threadfence();
                a = (f == 2) ? g_blk_pref[idx] : g_blk_agg[idx];
            }
            unsigned pm = __ballot_sync(0xffffffffu, idx >= 0 && f == 2);
            if (pm) {
                int stop = __ffs(pm) - 1;  // nearest block with full prefix
                int take = (idx >= 0 && lane <= stop) ? a : 0;
#pragma unroll
                for (int o = 16; o > 0; o >>= 1) take += __shfl_xor_sync(0xffffffffu, take, o);
                run += take;
                break;
            } else {
                int take = (idx >= 0) ? a : 0;
#pragma unroll
                for (int o = 16; o > 0; o >>= 1) take += __shfl_xor_sync(0xffffffffu, take, o);
                run += take;
                p -= 32;
            }
        }
        if (lane == 0) {
            sexc = run;
            g_blk_pref[bid] = run + total;
            __threadfence();
            g_blk_flag[bid] = 2;
        }
    }
    __syncthreads();
    if (i < NN) {
        g_rowptr[i] = sexc + wbase + incl - v;
        g_dinv[i] = rsqrtf((float)(v + 1));
    }
}

// scatter consumes rowptr: afterwards g_rowptr[n] == original rowptr[n+1]
__global__ void k_scatter(const int* __restrict__ src, const int* __restrict__ dst) {
    int i = blockIdx.x * blockDim.x + threadIdx.x;
    if (i < EE) {
        int d = dst[i];
        int pos = atomicAdd(&g_rowptr[d], 1);
        g_colsrc[pos] = src[i];
    }
}

// graph boundaries from sorted batch_idx
__global__ void k_gstart(const int* __restrict__ batch) {
    int n = blockIdx.x * blockDim.x + threadIdx.x;
    if (n >= NN) return;
    int b = batch[n];
    int prev = (n == 0) ? -1 : batch[n - 1];
    for (int g = prev + 1; g <= b; g++) g_gstart[g] = n;
    if (n == NN - 1) {
        for (int g = b + 1; g <= GG; g++) g_gstart[g] = NN;
    }
}

// ---------------- weight prep: fp16 transposed ------------------------------
__global__ void k_wprep(const float* __restrict__ W1, const float* __restrict__ W2) {
    int idx = blockIdx.x * blockDim.x + threadIdx.x;
    if (idx < 3 * 8192) {
        int l = idx >> 13, r = idx & 8191;
        int o = r >> 6, k = r & 63;
        g_W1T[idx] = __float2half(W1[l * 8192 + k * 128 + o]);
    } else if (idx < 6 * 8192) {
        int t = idx - 3 * 8192;
        int l = t >> 13, r = t & 8191;
        int n = r >> 7, k = r & 127;
        g_W2T[t] = __float2half(W2[l * 8192 + k * 64 + n]);
    }
}

// ---------------- x @ conv1_W, pre-scaled by dinv[n]; fp32 + fp16 ------------
__global__ void k_hx(const float* __restrict__ x, const float* __restrict__ W) {
    int idx = blockIdx.x * blockDim.x + threadIdx.x;
    if (idx >= NN * 32) return;
    int n = idx >> 5, p = idx & 31;
    float a0 = 0.f, a1 = 0.f;
#pragma unroll
    for (int f = 0; f < 5; f++) {
        float xv = x[n * 5 + f];
        a0 += xv * W[f * 64 + 2 * p];
        a1 += xv * W[f * 64 + 2 * p + 1];
    }
    float dn = g_dinv[n];
    a0 *= dn;
    a1 *= dn;
    float2 o;
    o.x = a0; o.y = a1;
    *reinterpret_cast<float2*>(&g_hx[n * 64 + 2 * p]) = o;
    g_hx16[n * 32 + p] = __floats2half2_rn(a0, a1);
}

// ---- GCNConv aggregate + BN + ReLU + fused layer-0 LN+PReLU -----------------
__global__ void k_gcn(const float* __restrict__ cb, const float* __restrict__ bg,
                      const float* __restrict__ bb, const float* __restrict__ lg,
                      const float* __restrict__ lb, const float* __restrict__ pa) {
    int tid = threadIdx.x;
    int n = blockIdx.x * 8 + (tid >> 5);
    int l = tid & 31;
    if (n >= NN) return;
    int b = (n == 0) ? 0 : g_rowptr[n - 1];
    int e = g_rowptr[n];
    float a0 = 0.f, a1 = 0.f;
    int i = b;
    for (; i + 8 <= e; i += 8) {
        int s0 = g_colsrc[i], s1 = g_colsrc[i + 1];
        int s2 = g_colsrc[i + 2], s3 = g_colsrc[i + 3];
        int s4 = g_colsrc[i + 4], s5 = g_colsrc[i + 5];
        int s6 = g_colsrc[i + 6], s7 = g_colsrc[i + 7];
        float2 f0 = __half22float2(g_hx16[s0 * 32 + l]);
        float2 f1 = __half22float2(g_hx16[s1 * 32 + l]);
        float2 f2 = __half22float2(g_hx16[s2 * 32 + l]);
        float2 f3 = __half22float2(g_hx16[s3 * 32 + l]);
        float2 f4 = __half22float2(g_hx16[s4 * 32 + l]);
        float2 f5 = __half22float2(g_hx16[s5 * 32 + l]);
        float2 f6 = __half22float2(g_hx16[s6 * 32 + l]);
        float2 f7 = __half22float2(g_hx16[s7 * 32 + l]);
        a0 += ((f0.x + f1.x) + (f2.x + f3.x)) + ((f4.x + f5.x) + (f6.x + f7.x));
        a1 += ((f0.y + f1.y) + (f2.y + f3.y)) + ((f4.y + f5.y) + (f6.y + f7.y));
    }
    for (; i < e; i++) {
        float2 f = __half22float2(g_hx16[g_colsrc[i] * 32 + l]);
        a0 += f.x;
        a1 += f.y;
    }
    float2 hx = *reinterpret_cast<const float2*>(&g_hx[n * 64 + 2 * l]);
    float dn = g_dinv[n];
    const float BNS = rsqrtf(1.f + 1e-5f);
    float v0 = (a0 + hx.x) * dn + cb[2 * l];
    float v1 = (a1 + hx.y) * dn + cb[2 * l + 1];
    v0 = fmaxf(v0 * (bg[2 * l] * BNS) + bb[2 * l], 0.f);
    v1 = fmaxf(v1 * (bg[2 * l + 1] * BNS) + bb[2 * l + 1], 0.f);
    float2 o; o.x = v0; o.y = v1;
    *reinterpret_cast<float2*>(&g_h[n * 64 + 2 * l]) = o;
    *reinterpret_cast<float2*>(&g_xcat[n * 256 + 2 * l]) = o;
    // fused layer-0 LayerNorm + PReLU -> u16
    float s = v0 + v1;
    float q = v0 * v0 + v1 * v1;
#pragma unroll
    for (int off = 16; off > 0; off >>= 1) {
        s += __shfl_xor_sync(0xffffffffu, s, off);
        q += __shfl_xor_sync(0xffffffffu, q, off);
    }
    float mu = s * (1.f / 64.f);
    float var = q * (1.f / 64.f) - mu * mu;
    float rs = rsqrtf(var + 1e-5f);
    float y0 = (v0 - mu) * rs * lg[2 * l] + lb[2 * l];
    y0 = (y0 >= 0.f) ? y0 : pa[2 * l] * y0;
    float y1 = (v1 - mu) * rs * lg[2 * l + 1] + lb[2 * l + 1];
    y1 = (y1 >= 0.f) ? y1 : pa[2 * l + 1] * y1;
    g_u16[n * 32 + l] = __floats2half2_rn(y0, y1);
}

// ---------------- LayerNorm + PReLU (layers 1,2): h -> u16 only --------------
__global__ void k_ln(const float* __restrict__ g, const float* __restrict__ b,
                     const float* __restrict__ a) {
    int tid = threadIdx.x;
    int n = blockIdx.x * 8 + (tid >> 5);
    int l = tid & 31;
    if (n >= NN) return;
    float2 v = *reinterpret_cast<const float2*>(&g_h[n * 64 + 2 * l]);
    float s = v.x + v.y;
    float q = v.x * v.x + v.y * v.y;
#pragma unroll
    for (int off = 16; off > 0; off >>= 1) {
        s += __shfl_xor_sync(0xffffffffu, s, off);
        q += __shfl_xor_sync(0xffffffffu, q, off);
    }
    float mu = s * (1.f / 64.f);
    float var = q * (1.f / 64.f) - mu * mu;
    float rs = rsqrtf(var + 1e-5f);
    float y0 = (v.x - mu) * rs * g[2 * l] + b[2 * l];
    y0 = (y0 >= 0.f) ? y0 : a[2 * l] * y0;
    float y1 = (v.y - mu) * rs * g[2 * l + 1] + b[2 * l + 1];
    y1 = (y1 >= 0.f) ? y1 : a[2 * l + 1] * y1;
    g_u16[n * 32 + l] = __floats2half2_rn(y0, y1);
}

// ---------------- GENConv softmax aggregation (warp per node, fp16) ----------
__global__ void k_gen(const float* __restrict__ gen_t, int layer) {
    int tid = threadIdx.x;
    int n = blockIdx.x * 8 + (tid >> 5);
    int l = tid & 31;
    if (n >= NN) return;
    float t = __ldg(&gen_t[layer]);
    int b = (n == 0) ? 0 : g_rowptr[n - 1];
    int e = g_rowptr[n];
    float s0 = 0.f, s1 = 0.f, ac0 = 0.f, ac1 = 0.f;
    int i = b;
    for (; i + 8 <= e; i += 8) {
#pragma unroll
        for (int z = 0; z < 8; z += 4) {
            int sA = g_colsrc[i + z], sB = g_colsrc[i + z + 1];
            int sC = g_colsrc[i + z + 2], sD = g_colsrc[i + z + 3];
            float2 fA = __half22float2(g_u16[sA * 32 + l]);
            float2 fB = __half22float2(g_u16[sB * 32 + l]);
            float2 fC = __half22float2(g_u16[sC * 32 + l]);
            float2 fD = __half22float2(g_u16[sD * 32 + l]);
            float vA0 = fmaxf(fA.x, 0.f) + 1e-7f, vA1 = fmaxf(fA.y, 0.f) + 1e-7f;
            float vB0 = fmaxf(fB.x, 0.f) + 1e-7f, vB1 = fmaxf(fB.y, 0.f) + 1e-7f;
            float vC0 = fmaxf(fC.x, 0.f) + 1e-7f, vC1 = fmaxf(fC.y, 0.f) + 1e-7f;
            float vD0 = fmaxf(fD.x, 0.f) + 1e-7f, vD1 = fmaxf(fD.y, 0.f) + 1e-7f;
            float eA0 = __expf(vA0 * t), eA1 = __expf(vA1 * t);
            float eB0 = __expf(vB0 * t), eB1 = __expf(vB1 * t);
            float eC0 = __expf(vC0 * t), eC1 = __expf(vC1 * t);
            float eD0 = __expf(vD0 * t), eD1 = __expf(vD1 * t);
            s0 += (eA0 + eB0) + (eC0 + eD0);
            s1 += (eA1 + eB1) + (eC1 + eD1);
            ac0 += (vA0 * eA0 + vB0 * eB0) + (vC0 * eC0 + vD0 * eD0);
            ac1 += (vA1 * eA1 + vB1 * eB1) + (vC1 * eC1 + vD1 * eD1);
        }
    }
    for (; i < e; i++) {
        float2 f = __half22float2(g_u16[g_colsrc[i] * 32 + l]);
        float v0 = fmaxf(f.x, 0.f) + 1e-7f;
        float v1 = fmaxf(f.y, 0.f) + 1e-7f;
        float e0 = __expf(v0 * t), e1 = __expf(v1 * t);
        s0 += e0; s1 += e1;
        ac0 += v0 * e0; ac1 += v1 * e1;
    }
    float2 u = __half22float2(g_u16[n * 32 + l]);
    float o0 = ((e > b) ? (ac0 / s0) : 0.f) + u.x;
    float o1 = ((e > b) ? (ac1 / s1) : 0.f) + u.y;
    g_agg16[n * 32 + l] = __floats2half2_rn(o0, o1);
}

// ---------------- HMMA fused MLP (exact R8 version) --------------------------
#define STA 72    // halves per A row (144B)
#define STW2 136  // halves per W2 row (272B)

__device__ __forceinline__ void ldmx4(uint32_t addr, uint32_t& a0, uint32_t& a1,
                                      uint32_t& a2, uint32_t& a3) {
    asm volatile("ldmatrix.sync.aligned.m8n8.x4.shared.b16 {%0,%1,%2,%3}, [%4];"
                 : "=r"(a0), "=r"(a1), "=r"(a2), "=r"(a3) : "r"(addr));
}
__device__ __forceinline__ void ldmx2(uint32_t addr, uint32_t& b0, uint32_t& b1) {
    asm volatile("ldmatrix.sync.aligned.m8n8.x2.shared.b16 {%0,%1}, [%2];"
                 : "=r"(b0), "=r"(b1) : "r"(addr));
}
__device__ __forceinline__ void mma16816(float* c, const uint32_t* a, const uint32_t* b) {
    asm volatile("mma.sync.aligned.m16n8k16.row.col.f32.f16.f16.f32 "
                 "{%0,%1,%2,%3}, {%4,%5,%6,%7}, {%8,%9}, {%0,%1,%2,%3};"
                 : "+f"(c[0]), "+f"(c[1]), "+f"(c[2]), "+f"(c[3])
                 : "r"(a[0]), "r"(a[1]), "r"(a[2]), "r"(a[3]), "r"(b[0]), "r"(b[1]));
}

__global__ void __launch_bounds__(256)
k_mma(const float* __restrict__ b1, const float* __restrict__ bng,
      const float* __restrict__ bnb, const float* __restrict__ b2, int layer) {
    extern __shared__ char smem[];
    float*  mpar = (float*)smem;              // 128
    float*  apar = mpar + 128;                // 128
    __half* sA   = (__half*)(apar + 128);     // 128*STA
    __half* sW1  = sA + 128 * STA;            // 128*STA
    __half* sW2  = sW1 + 128 * STA;           // 64*STW2
    int tid = threadIdx.x;
    int n0 = blockIdx.x * 128;

    if (tid < 128) {
        const float BNS = rsqrtf(1.f + 1e-5f);
        float m = __ldg(&bng[tid]) * BNS;
        mpar[tid] = m;
        apar[tid] = __ldg(&b1[tid]) * m + __ldg(&bnb[tid]);
    }
    for (int i = tid; i < 128 * 32; i += 256) {
        int r = i >> 5, p = i & 31;
        int n = n0 + r;
        __half2 v = (n < NN) ? g_agg16[n * 32 + p] : __floats2half2_rn(0.f, 0.f);
        *(__half2*)&sA[r * STA + 2 * p] = v;
    }
    const __half* w1p = g_W1T + layer * 8192;
    for (int i = tid; i < 128 * 32; i += 256) {
        int r = i >> 5, p = i & 31;
        *(__half2*)&sW1[r * STA + 2 * p] = *(const __half2*)&w1p[r * 64 + 2 * p];
    }
    const __half* w2p = g_W2T + layer * 8192;
    for (int i = tid; i < 64 * 64; i += 256) {
        int r = i >> 6, p = i & 63;
        *(__half2*)&sW2[r * STW2 + 2 * p] = *(const __half2*)&w2p[r * 128 + 2 * p];
    }
    __syncthreads();

    int wid = tid >> 5, lane = tid & 31;
    int m0 = wid * 16;

    float c[16][4];
#pragma unroll
    for (int nt = 0; nt < 16; nt++)
#pragma unroll
        for (int q = 0; q < 4; q++) c[nt][q] = 0.f;

    int arow = m0 + (lane & 7) + ((lane >> 3) & 1) * 8;
    int acolbase = (lane >> 4) * 8;
    int brow = (lane & 7);
    int bcolbase = ((lane >> 3) & 1) * 8;
#pragma unroll
    for (int kt = 0; kt < 4; kt++) {
        uint32_t a[4];
        ldmx4(smem_u32(&sA[arow * STA + kt * 16 + acolbase]), a[0], a[1], a[2], a[3]);
#pragma unroll
        for (int nt = 0; nt < 16; nt++) {
            uint32_t b[2];
            ldmx2(smem_u32(&sW1[(nt * 8 + brow) * STA + kt * 16 + bcolbase]), b[0], b[1]);
            mma16816(c[nt], a, b);
        }
    }

    int ob = (lane & 3) * 2;
    uint32_t az[8][4];
#pragma unroll
    for (int nt = 0; nt < 16; nt++) {
        int o0 = nt * 8 + ob, o1 = o0 + 1;
        float m0f = mpar[o0], m1f = mpar[o1];
        float a0f = apar[o0], a1f = apar[o1];
        float z0 = fmaxf(c[nt][0] * m0f + a0f, 0.f);
        float z1 = fmaxf(c[nt][1] * m1f + a1f, 0.f);
        float z2 = fmaxf(c[nt][2] * m0f + a0f, 0.f);
        float z3 = fmaxf(c[nt][3] * m1f + a1f, 0.f);
        __half2 p01 = __floats2half2_rn(z0, z1);
        __half2 p23 = __floats2half2_rn(z2, z3);
        az[nt >> 1][(nt & 1) * 2 + 0] = *(uint32_t*)&p01;
        az[nt >> 1][(nt & 1) * 2 + 1] = *(uint32_t*)&p23;
    }

    float d[8][4];
#pragma unroll
    for (int nt = 0; nt < 8; nt++)
#pragma unroll
        for (int q = 0; q < 4; q++) d[nt][q] = 0.f;
#pragma unroll
    for (int kt = 0; kt < 8; kt++) {
#pragma unroll
        for (int nt = 0; nt < 8; nt++) {
            uint32_t b[2];
            ldmx2(smem_u32(&sW2[(nt * 8 + brow) * STW2 + kt * 16 + bcolbase]), b[0], b[1]);
            mma16816(d[nt], az[kt], b);
        }
    }

    int r0 = n0 + m0 + (lane >> 2);
    int r1 = r0 + 8;
    int xoff = (layer + 1) * 64;
#pragma unroll
    for (int nt = 0; nt < 8; nt++) {
        int o0 = nt * 8 + ob;
        float bb0 = __ldg(&b2[o0]);
        float bb1 = __ldg(&b2[o0 + 1]);
        if (r0 < NN) {
            float2 hv = *(float2*)&g_h[r0 * 64 + o0];
            float2 nh;
            nh.x = hv.x + d[nt][0] + bb0;
            nh.y = hv.y + d[nt][1] + bb1;
            *(float2*)&g_h[r0 * 64 + o0] = nh;
            *(float2*)&g_xcat[r0 * 256 + xoff + o0] = nh;
        }
        if (r1 < NN) {
            float2 hv = *(float2*)&g_h[r1 * 64 + o0];
            float2 nh;
            nh.x = hv.x + d[nt][2] + bb0;
            nh.y = hv.y + d[nt][3] + bb1;
            *(float2*)&g_h[r1 * 64 + o0] = nh;
            *(float2*)&g_xcat[r1 * 256 + xoff + o0] = nh;
        }
    }
}
#define MMA_SMEM (256 * 4 + (128 * STA + 128 * STA + 64 * STW2) * 2)

// ---------------- fused pooling + readout MLP --------------------------------
__global__ void k_poolread(const float* __restrict__ W1, const float* __restrict__ b1,
                           const float* __restrict__ W2, const float* __restrict__ b2,
                           const float* __restrict__ Wo, const float* __restrict__ bo,
                           float* __restrict__ out) {
    __shared__ float p[512];
    __shared__ float q1[128];
    __shared__ float q2[64];
    int g = blockIdx.x;
    int tid = threadIdx.x;   // 256
    int beg = g_gstart[g], end = g_gstart[g + 1];
    float sum = 0.f, mx = -INFINITY;
    for (int n = beg; n < end; n++) {
        float v = g_xcat[n * 256 + tid];
        sum += v;
        mx = fmaxf(mx, v);
    }
    float c = (float)(end - beg);
    p[tid] = sum / fmaxf(c, 1.f);
    p[256 + tid] = (end > beg) ? mx : 0.f;
    __syncthreads();
    if (tid < 128) {
        float a = b1[tid];
        for (int k = 0; k < 512; k++) a += p[k] * W1[k * 128 + tid];
        q1[tid] = fmaxf(a, 0.f);
    }
    __syncthreads();
    if (tid < 64) {
        float a = b2[tid];
        for (int k = 0; k < 128; k++) a += q1[k] * W2[k * 64 + tid];
        q2[tid] = fmaxf(a, 0.f);
    }
    __syncthreads();
    if (tid < 32) {
        float s = q2[tid] * Wo[tid] + q2[tid + 32] * Wo[tid + 32];
#pragma unroll
        for (int off = 16; off > 0; off >>= 1) s += __shfl_xor_sync(0xffffffffu, s, off);
        if (tid == 0) out[g] = s + bo[0];
    }
}

// ---------------- launch -----------------------------------------------------
extern "C" void kernel_launch(void* const* d_in, const int* in_sizes, int n_in,
                              void* d_out, int out_size) {
    const float* x        = (const float*)d_in[0];
    const int*   ei       = (const int*)d_in[1];
    const int*   batch    = (const int*)d_in[2];
    const float* conv1_W  = (const float*)d_in[3];
    const float* conv1_b  = (const float*)d_in[4];
    const float* bn1_g    = (const float*)d_in[5];
    const float* bn1_b    = (const float*)d_in[6];
    const float* ln_g     = (const float*)d_in[7];
    const float* ln_b     = (const float*)d_in[8];
    const float* prelu_a  = (const float*)d_in[9];
    const float* gen_t    = (const float*)d_in[10];
    const float* mlp_W1   = (const float*)d_in[11];
    const float* mlp_b1   = (const float*)d_in[12];
    const float* mlp_bn_g = (const float*)d_in[13];
    const float* mlp_bn_b = (const float*)d_in[14];
    const float* mlp_W2   = (const float*)d_in[15];
    const float* mlp_b2   = (const float*)d_in[16];
    const float* lin1_W   = (const float*)d_in[17];
    const float* lin1_b   = (const float*)d_in[18];
    const float* lin2_W   = (const float*)d_in[19];
    const float* lin2_b   = (const float*)d_in[20];
    const float* out_W    = (const float*)d_in[21];
    const float* out_b    = (const float*)d_in[22];
    float* out = (float*)d_out;

    const int* src = ei;
    const int* dst = ei + EE;

    static int smem_set = 0;
    if (!smem_set) {
        cudaFuncSetAttribute(k_mma, cudaFuncAttributeMaxDynamicSharedMemorySize, MMA_SMEM);
        smem_set = 1;
    }

    k_init<<<NBLK, 256>>>();
    k_hist<<<(EE + 255) / 256, 256>>>(dst);
    k_scanlb<<<NBLK, 256>>>();
    k_scatter<<<(EE + 255) / 256, 256>>>(src, dst);
    k_hx<<<(NN * 32 + 255) / 256, 256>>>(x, conv1_W);
    k_gcn<<<(NN + 7) / 8, 256>>>(conv1_b, bn1_g, bn1_b, ln_g, ln_b, prelu_a);  // slot 6: profiled
    k_gstart<<<NBLK, 256>>>(batch);
    k_wprep<<<192, 256>>>(mlp_W1, mlp_W2);

    for (int i = 0; i < 3; i++) {
        if (i > 0) k_ln<<<(NN + 7) / 8, 256>>>(ln_g + i * 64, ln_b + i * 64, prelu_a + i * 64);
        k_gen<<<(NN + 7) / 8, 256>>>(gen_t, i);
        k_mma<<<(NN + 127) / 128, 256, MMA_SMEM>>>(mlp_b1 + i * 128, mlp_bn_g + i * 128,
                                                   mlp_bn_b + i * 128, mlp_b2 + i * 64, i);
    }

    k_poolread<<<GG, 256>>>(lin1_W, lin1_b, lin2_W, lin2_b, out_W, out_b, out);
}